// round 13
// baseline (speedup 1.0000x reference)
#include <cuda_runtime.h>
#include <cuda_bf16.h>
#include <math.h>
#include <stdint.h>

// Problem constants
#define Bn 4
#define Tn 1024
#define Cn 1024
#define Hn 16
#define Dn 64
#define MR (Bn*Tn)
#define BH (Bn*Hn)

// ---------------- scratch (no allocations allowed) ----------------
__device__ float g_qkv[MR * 3 * Cn];
__device__ float g_spk[MR];
__device__ float g_y  [MR * Cn];
__device__ __nv_bfloat16 g_xh[MR * Cn], g_xl[MR * Cn];
__device__ __nv_bfloat16 g_yh[MR * Cn], g_yl[MR * Cn];
__device__ __nv_bfloat16 g_wqh[3 * Cn * Cn], g_wql[3 * Cn * Cn];
__device__ __nv_bfloat16 g_woh[Cn * Cn], g_wol[Cn * Cn];
__device__ __nv_bfloat16 g_qth[BH * Tn * Dn], g_qtl[BH * Tn * Dn];
__device__ __nv_bfloat16 g_kth[BH * Tn * Dn], g_ktl[BH * Tn * Dn];
__device__ __nv_bfloat16 g_vth[BH * Dn * Tn], g_vtl[BH * Dn * Tn];

// ---------------- helpers ----------------
__device__ __forceinline__ uint32_t smem_u32(const void* p) {
    uint32_t a;
    asm("{ .reg .u64 t; cvta.to.shared.u64 t, %1; cvt.u32.u64 %0, t; }" : "=r"(a) : "l"(p));
    return a;
}
__device__ __forceinline__ void cp16(uint32_t dst, const void* src) {
    asm volatile("cp.async.cg.shared.global [%0], [%1], 16;" :: "r"(dst), "l"(src));
}
__device__ __forceinline__ void cp_commit() {
    asm volatile("cp.async.commit_group;" ::: "memory");
}
template <int N>
__device__ __forceinline__ void cp_wait() {
    asm volatile("cp.async.wait_group %0;" :: "n"(N) : "memory");
}
__device__ __forceinline__ void mma16816(float* d, const uint32_t* a, const uint32_t* b) {
    asm volatile(
        "mma.sync.aligned.m16n8k16.row.col.f32.bf16.bf16.f32 "
        "{%0,%1,%2,%3}, {%4,%5,%6,%7}, {%8,%9}, {%0,%1,%2,%3};"
        : "+f"(d[0]), "+f"(d[1]), "+f"(d[2]), "+f"(d[3])
        : "r"(a[0]), "r"(a[1]), "r"(a[2]), "r"(a[3]), "r"(b[0]), "r"(b[1]));
}
__device__ __forceinline__ void ldsm4(uint32_t* r, uint32_t addr) {
    asm volatile("ldmatrix.sync.aligned.m8n8.x4.shared.b16 {%0,%1,%2,%3}, [%4];"
        : "=r"(r[0]), "=r"(r[1]), "=r"(r[2]), "=r"(r[3]) : "r"(addr));
}
__device__ __forceinline__ uint32_t pack_bf16x2(float hi, float lo) {
    uint32_t r;
    asm("cvt.rn.bf16x2.f32 %0, %1, %2;" : "=r"(r) : "f"(hi), "f"(lo));
    return r;
}

// ---------------- fast math (FMA-pipe log/exp) ----------------
__device__ __forceinline__ float fast_log(float a) {   // a >= 1
    int i = __float_as_int(a);
    int e = (i >> 23) - 126;
    float m = __int_as_float((i & 0x007FFFFF) | 0x3F000000);
    if (m < 0.70710678118f) { m = m + m; e -= 1; }
    float x = m - 1.0f;
    float z = x * x;
    float y = 7.0376836292e-2f;
    y = fmaf(y, x, -1.1514610310e-1f);
    y = fmaf(y, x,  1.1676998740e-1f);
    y = fmaf(y, x, -1.2420140846e-1f);
    y = fmaf(y, x,  1.4249322787e-1f);
    y = fmaf(y, x, -1.6668057665e-1f);
    y = fmaf(y, x,  2.0000714765e-1f);
    y = fmaf(y, x, -2.4999993993e-1f);
    y = fmaf(y, x,  3.3333331174e-1f);
    y = y * x * z;
    float ef = (float)e;
    y = fmaf(ef, -2.12194440e-4f, y);
    y = fmaf(-0.5f, z, y);
    float r = x + y;
    return fmaf(ef, 0.693359375f, r);
}
__device__ __forceinline__ float fast_exp_neg(float zin) {  // zin <= 0
    float z = fmaxf(zin, -80.f);
    float fn = fmaf(z, 1.44269504089f, 12582912.f);
    int n = __float_as_int(fn) - 0x4B400000;
    float nf = fn - 12582912.f;
    float r = fmaf(nf, -0.693359375f, z);
    r = fmaf(nf, 2.12194440e-4f, r);
    float y = 1.9875691500e-4f;
    y = fmaf(y, r, 1.3981999507e-3f);
    y = fmaf(y, r, 8.3334519073e-3f);
    y = fmaf(y, r, 4.1665795894e-2f);
    y = fmaf(y, r, 1.6666665459e-1f);
    y = fmaf(y, r, 5.0000001201e-1f);
    float res = fmaf(y * r, r, r) + 1.0f;
    return res * __int_as_float((n + 127) << 23);
}
__device__ __forceinline__ float score_p(float x) {
    float xx = fmaxf(x, 1.0000001f);
    float s2 = fmaf(xx, xx, -1.f);
    float sq;
    asm("sqrt.approx.f32 %0, %1;" : "=f"(sq) : "f"(s2));
    float dist = fast_log(xx + sq);
    return fast_exp_neg(dist * dist * -0.125f);
}

// ---------------- spike / surrogate ----------------
__global__ void spike_kernel(const float* __restrict__ x, const float* __restrict__ w_sur,
                             const float* __restrict__ b_sur, const float* __restrict__ threshold,
                             float* __restrict__ spikes) {
    __shared__ float red[256];
    int bt = blockIdx.x;
    const float* xr = &x[(size_t)bt * Cn];
    float s = 0.f;
    for (int c = threadIdx.x; c < Cn; c += 256) s += xr[c] * w_sur[c];
    red[threadIdx.x] = s;
    __syncthreads();
    for (int o = 128; o; o >>= 1) {
        if (threadIdx.x < o) red[threadIdx.x] += red[threadIdx.x + o];
        __syncthreads();
    }
    if (threadIdx.x == 0) {
        float imp = 1.f / (1.f + expf(-(red[0] + b_sur[0])));
        spikes[bt] = imp > threshold[0] ? 1.f : 0.f;
    }
}

// ---------------- fp32 -> bf16 hi/lo converters ----------------
__global__ void conv_rows_kernel(const float* __restrict__ A,
                                 __nv_bfloat16* __restrict__ h, __nv_bfloat16* __restrict__ l) {
    int i = blockIdx.x * 256 + threadIdx.x;
    float v = A[i];
    __nv_bfloat16 hh = __float2bfloat16(v);
    h[i] = hh;
    l[i] = __float2bfloat16(v - __bfloat162float(hh));
}
__global__ void convT_kernel(const float* __restrict__ W,
                             __nv_bfloat16* __restrict__ th, __nv_bfloat16* __restrict__ tl,
                             int K, int N) {
    __shared__ float t[32][33];
    int n0 = blockIdx.x * 32, k0 = blockIdx.y * 32;
    for (int i = threadIdx.y; i < 32; i += 8)
        t[i][threadIdx.x] = W[(size_t)(k0 + i) * N + n0 + threadIdx.x];
    __syncthreads();
    for (int i = threadIdx.y; i < 32; i += 8) {
        float v = t[threadIdx.x][i];
        __nv_bfloat16 hh = __float2bfloat16(v);
        size_t o = (size_t)(n0 + i) * K + k0 + threadIdx.x;
        th[o] = hh;
        tl[o] = __float2bfloat16(v - __bfloat162float(hh));
    }
}

// ---------------- mma.sync split-bf16 GEMM: 128x256 tile, 512 thr, 1 sync/chunk ----------------
#define G2_AH 0
#define G2_AL 10240
#define G2_BH 20480
#define G2_BL 40960
#define G2_STAGE 61440
#define GEMM_SMEM (2 * G2_STAGE)

__global__ __launch_bounds__(512) void mma_gemm_kernel(
    const __nv_bfloat16* __restrict__ Ah, const __nv_bfloat16* __restrict__ Al,
    const __nv_bfloat16* __restrict__ Bh, const __nv_bfloat16* __restrict__ Bl,
    const float* __restrict__ bias, float* __restrict__ Cm, int N, int K) {
    extern __shared__ __align__(128) char smem[];
    uint32_t sb = smem_u32(smem);

    int tid = threadIdx.x;
    int lane = tid & 31;
    int w = tid >> 5;            // 0..15
    int wm = w & 3;              // 4 M warp-tiles of 32
    int wn = w >> 2;             // 4 N warp-tiles of 64
    int bm = blockIdx.y * 128;
    int bn = blockIdx.x * 256;

    float acc[2][8][4];
#pragma unroll
    for (int mt = 0; mt < 2; mt++)
#pragma unroll
        for (int nt = 0; nt < 8; nt++)
#pragma unroll
            for (int q = 0; q < 4; q++) acc[mt][nt][q] = 0.f;

    int NK = K / 32;

    auto load_stage = [&](int kc, int s) {
        uint32_t base = sb + s * G2_STAGE;
        int k0 = kc * 32;
        {   // A: 128 rows x 4 chunks x 2 planes -> 1 cp16/plane/thread
            int r = tid >> 2, c = tid & 3;
            uint32_t so = (uint32_t)(r * 80 + c * 16);
            size_t go = (size_t)(bm + r) * K + k0 + c * 8;
            cp16(base + G2_AH + so, Ah + go);
            cp16(base + G2_AL + so, Al + go);
        }
#pragma unroll
        for (int it = 0; it < 2; it++) {   // B: 256 rows x 4 chunks x 2 planes
            int lin = it * 512 + tid;
            int r = lin >> 2, c = lin & 3;
            uint32_t so = (uint32_t)(r * 80 + c * 16);
            size_t go = (size_t)(bn + r) * K + k0 + c * 8;
            cp16(base + G2_BH + so, Bh + go);
            cp16(base + G2_BL + so, Bl + go);
        }
        cp_commit();
    };

    load_stage(0, 0);

    uint32_t l15 = lane & 15;
    uint32_t lhi = (lane >> 4) * 16;

    for (int kc = 0; kc < NK; kc++) {
        cp_wait<0>();              // my loads for chunk kc done
        __syncthreads();           // publish stage kc; all readers of stage kc-1 done
        if (kc + 1 < NK) load_stage(kc + 1, (kc + 1) & 1);   // overlaps compute(kc)

        uint32_t base = sb + (kc & 1) * G2_STAGE;

#pragma unroll
        for (int ks = 0; ks < 2; ks++) {
            uint32_t ah[2][4], al[2][4];
#pragma unroll
            for (int mt = 0; mt < 2; mt++) {
                uint32_t off = (uint32_t)((wm * 32 + mt * 16 + l15) * 80) + ks * 32 + lhi;
                ldsm4(ah[mt], base + G2_AH + off);
                ldsm4(al[mt], base + G2_AL + off);
            }
#pragma unroll
            for (int ntp = 0; ntp < 4; ntp++) {
                uint32_t off = (uint32_t)((wn * 64 + ntp * 16 + l15) * 80) + ks * 32 + lhi;
                uint32_t bhp[4], blp[4];
                ldsm4(bhp, base + G2_BH + off);
                ldsm4(blp, base + G2_BL + off);
#pragma unroll
                for (int sub = 0; sub < 2; sub++) {
                    int nt = ntp * 2 + sub;
                    uint32_t bh2[2] = { bhp[sub], bhp[2 + sub] };
                    uint32_t bl2[2] = { blp[sub], blp[2 + sub] };
#pragma unroll
                    for (int mt = 0; mt < 2; mt++) {
                        mma16816(acc[mt][nt], ah[mt], bh2);
                        mma16816(acc[mt][nt], ah[mt], bl2);
                        mma16816(acc[mt][nt], al[mt], bh2);
                    }
                }
            }
        }
    }

#pragma unroll
    for (int mt = 0; mt < 2; mt++) {
        int m0 = bm + wm * 32 + mt * 16 + (lane >> 2);
#pragma unroll
        for (int nt = 0; nt < 8; nt++) {
            int c0 = bn + wn * 64 + nt * 8 + 2 * (lane & 3);
            float b0 = bias[c0], b1 = bias[c0 + 1];
            float* p0 = Cm + (size_t)m0 * N + c0;
            p0[0] = acc[mt][nt][0] + b0;
            p0[1] = acc[mt][nt][1] + b1;
            float* p1 = p0 + 8 * (size_t)N;
            p1[0] = acc[mt][nt][2] + b0;
            p1[1] = acc[mt][nt][3] + b1;
        }
    }
}

// ---------------- expmap0 transform: 32 tokens x 1 head per block ----------------
__global__ __launch_bounds__(256) void transform_kernel(
    const float* __restrict__ qkv,
    __nv_bfloat16* __restrict__ qth, __nv_bfloat16* __restrict__ qtl,
    __nv_bfloat16* __restrict__ kth, __nv_bfloat16* __restrict__ ktl,
    __nv_bfloat16* __restrict__ vth, __nv_bfloat16* __restrict__ vtl) {
    __shared__ float vs[32][67];

    int tb = blockIdx.x;
    int h = blockIdx.y;
    int w = threadIdx.x >> 5;
    int lane = threadIdx.x & 31;

    int bt0 = tb * 32;
    int b = bt0 / Tn;
    int t0 = bt0 % Tn;
    int bh = b * Hn + h;

#pragma unroll
    for (int it = 0; it < 4; it++) {
        int tl = it * 8 + w;
        int bt = bt0 + tl;
        int t = t0 + tl;

        const float* base = &qkv[(size_t)bt * (3 * Cn) + h * Dn];
        float2 uq = ((const float2*)base)[lane];
        float2 uk = ((const float2*)(base + Cn))[lane];
        float2 uv = ((const float2*)(base + 2 * Cn))[lane];

        float sq = uq.y * uq.y + (lane ? uq.x * uq.x : 0.f);
        float sk = uk.y * uk.y + (lane ? uk.x * uk.x : 0.f);
#pragma unroll
        for (int off = 16; off; off >>= 1) {
            sq += __shfl_xor_sync(0xFFFFFFFFu, sq, off);
            sk += __shfl_xor_sync(0xFFFFFFFFu, sk, off);
        }
        float u0q = __shfl_sync(0xFFFFFFFFu, uq.x, 0);
        float u0k = __shfl_sync(0xFFFFFFFFu, uk.x, 0);

        float nq = sqrtf(fmaxf(sq - u0q * u0q, 1e-8f));
        float nk = sqrtf(fmaxf(sk - u0k * u0k, 1e-8f));
        float fq = sinhf(nq) / nq;
        float fk = sinhf(nk) / nk;
        float tmq = coshf(nq);
        float tmk = coshf(nk);

        float2 oq, ok;
        oq.x = lane ? fq * uq.x : tmq;
        oq.y = fq * uq.y;
        ok.x = lane ? -fk * uk.x : tmk;
        ok.y = -fk * uk.y;

        size_t out = ((size_t)bh * Tn + t) * Dn;
        __nv_bfloat16 qx = __float2bfloat16(oq.x), qy = __float2bfloat16(oq.y);
        ((__nv_bfloat162*)(qth + out))[lane] = __nv_bfloat162(qx, qy);
        ((__nv_bfloat162*)(qtl + out))[lane] = __nv_bfloat162(
            __float2bfloat16(oq.x - __bfloat162float(qx)), __float2bfloat16(oq.y - __bfloat162float(qy)));
        __nv_bfloat16 kx = __float2bfloat16(ok.x), ky = __float2bfloat16(ok.y);
        ((__nv_bfloat162*)(kth + out))[lane] = __nv_bfloat162(kx, ky);
        ((__nv_bfloat162*)(ktl + out))[lane] = __nv_bfloat162(
            __float2bfloat16(ok.x - __bfloat162float(kx)), __float2bfloat16(ok.y - __bfloat162float(ky)));

        vs[tl][2 * lane] = uv.x;
        vs[tl][2 * lane + 1] = uv.y;
    }
    __syncthreads();

#pragma unroll
    for (int rep = 0; rep < 8; rep++) {
        int idx = rep * 256 + threadIdx.x;
        int d = idx >> 5, t = idx & 31;
        float v = vs[t][d];
        __nv_bfloat16 hh = __float2bfloat16(v);
        size_t o = ((size_t)bh * Dn + d) * Tn + t0 + t;
        vth[o] = hh;
        vtl[o] = __float2bfloat16(v - __bfloat162float(hh));
    }
}

// ---------------- flash attention on mma.sync + ldmatrix (unchanged from R10) ----------------
#define ATK_OFF 0
#define ATKL_OFF 9216
#define ATV_OFF 18432
#define ATVL_OFF 27648
#define ATSTG 36864
#define ATTN_SMEM (2 * ATSTG)

__global__ __launch_bounds__(256) void attn_mma_kernel(
    const __nv_bfloat16* __restrict__ qth, const __nv_bfloat16* __restrict__ qtl,
    const __nv_bfloat16* __restrict__ kth, const __nv_bfloat16* __restrict__ ktl,
    const __nv_bfloat16* __restrict__ vth, const __nv_bfloat16* __restrict__ vtl,
    const float* __restrict__ spikes, float* __restrict__ y) {
    extern __shared__ __align__(128) char smem[];
    uint32_t sb = smem_u32(smem);

    int tid = threadIdx.x;
    int lane = tid & 31;
    int w = tid >> 5;

    int idx = blockIdx.x;
    int qt = 7 - (idx >> 6);
    int bh = idx & 63;
    int b = bh >> 4, h = bh & 15;
    int q0 = qt * 128;

    size_t qoff = ((size_t)bh * Tn + q0) * Dn;
#pragma unroll
    for (int it = 0; it < 4; it++) {
        int lin = it * 256 + tid;
        int r = lin >> 3, c = lin & 7;
        cp16(sb + (uint32_t)(r * 144 + c * 16), qth + qoff + r * 64 + c * 8);
        cp16(sb + 18432u + (uint32_t)(r * 144 + c * 16), qtl + qoff + r * 64 + c * 8);
    }
    cp_commit();

    size_t kbase = (size_t)bh * Tn * Dn;
    size_t vbase = (size_t)bh * Dn * Tn;
    auto load_tile = [&](int t, int s) {
        uint32_t base = sb + s * ATSTG;
        int k0 = t * 64;
#pragma unroll
        for (int it = 0; it < 2; it++) {
            int lin = it * 256 + tid;
            int r = lin >> 3, c = lin & 7;
            uint32_t so = (uint32_t)(r * 144 + c * 16);
            cp16(base + ATK_OFF + so, kth + kbase + (size_t)(k0 + r) * 64 + c * 8);
            cp16(base + ATKL_OFF + so, ktl + kbase + (size_t)(k0 + r) * 64 + c * 8);
            cp16(base + ATV_OFF + so, vth + vbase + (size_t)r * Tn + k0 + c * 8);
            cp16(base + ATVL_OFF + so, vtl + vbase + (size_t)r * Tn + k0 + c * 8);
        }
        cp_commit();
    };

    load_tile(0, 1);

    cp_wait<1>();
    __syncthreads();

    int rowi = lane >> 2;
    int qrow = w * 16 + rowi;
    uint32_t qfh[4][4], qfl[4][4];
#pragma unroll
    for (int ks = 0; ks < 4; ks++) {
        int cb = (ks * 16 + 2 * (lane & 3)) * 2;
        const char* qs = smem;
        const char* qsl = smem + 18432;
        qfh[ks][0] = *(const uint32_t*)(qs + qrow * 144 + cb);
        qfh[ks][1] = *(const uint32_t*)(qs + (qrow + 8) * 144 + cb);
        qfh[ks][2] = *(const uint32_t*)(qs + qrow * 144 + cb + 16);
        qfh[ks][3] = *(const uint32_t*)(qs + (qrow + 8) * 144 + cb + 16);
        qfl[ks][0] = *(const uint32_t*)(qsl + qrow * 144 + cb);
        qfl[ks][1] = *(const uint32_t*)(qsl + (qrow + 8) * 144 + cb);
        qfl[ks][2] = *(const uint32_t*)(qsl + qrow * 144 + cb + 16);
        qfl[ks][3] = *(const uint32_t*)(qsl + (qrow + 8) * 144 + cb + 16);
    }
    __syncthreads();

    float O[8][4];
#pragma unroll
    for (int nt = 0; nt < 8; nt++)
#pragma unroll
        for (int q = 0; q < 4; q++) O[nt][q] = 0.f;
    float l0 = 0.f, l1 = 0.f;

    int r0g = q0 + w * 16 + rowi;
    int r1g = r0g + 8;

    uint32_t l15 = lane & 15;
    uint32_t lhi = (lane >> 4) * 16;

    int ntiles = qt * 2 + 2;
    for (int t = 0; t < ntiles; t++) {
        if (t + 1 < ntiles) { load_tile(t + 1, t & 1); cp_wait<1>(); }
        else cp_wait<0>();
        __syncthreads();

        int s = (t + 1) & 1;
        uint32_t stg = sb + s * ATSTG;
        int k0 = t * 64;

        float S[8][4];
#pragma unroll
        for (int nt = 0; nt < 8; nt++)
#pragma unroll
            for (int q = 0; q < 4; q++) S[nt][q] = 0.f;
#pragma unroll
        for (int ks = 0; ks < 4; ks++) {
#pragma unroll
            for (int ntp = 0; ntp < 4; ntp++) {
                uint32_t off = (ntp * 16 + l15) * 144 + ks * 32 + lhi;
                uint32_t bhp[4], blp[4];
                ldsm4(bhp, stg + ATK_OFF + off);
                ldsm4(blp, stg + ATKL_OFF + off);
#pragma unroll
                for (int sub = 0; sub < 2; sub++) {
                    int nt = ntp * 2 + sub;
                    uint32_t bh2[2] = { bhp[sub], bhp[2 + sub] };
                    uint32_t bl2[2] = { blp[sub], blp[2 + sub] };
                    mma16816(S[nt], qfh[ks], bh2);
                    mma16816(S[nt], qfh[ks], bl2);
                    mma16816(S[nt], qfl[ks], bh2);
                }
            }
        }

        uint32_t pha[4][4], pla[4][4];
#pragma unroll
        for (int nt = 0; nt < 8; nt++) {
            int jj0 = k0 + nt * 8 + 2 * (lane & 3);
            float p0 = score_p(S[nt][0]);
            float p1 = score_p(S[nt][1]);
            float p2 = score_p(S[nt][2]);
            float p3 = score_p(S[nt][3]);
            p0 = (jj0 <= r0g) ? p0 : 0.f;
            p1 = (jj0 + 1 <= r0g) ? p1 : 0.f;
            p2 = (jj0 <= r1g) ? p2 : 0.f;
            p3 = (jj0 + 1 <= r1g) ? p3 : 0.f;
            l0 += p0 + p1;
            l1 += p2 + p3;
            uint32_t h01 = pack_bf16x2(p1, p0);
            uint32_t h23 = pack_bf16x2(p3, p2);
            float f0 = __int_as_float(h01 << 16);
            float f1 = __int_as_float(h01 & 0xFFFF0000u);
            float f2 = __int_as_float(h23 << 16);
            float f3 = __int_as_float(h23 & 0xFFFF0000u);
            uint32_t l01 = pack_bf16x2(p1 - f1, p0 - f0);
            uint32_t l23 = pack_bf16x2(p3 - f3, p2 - f2);
            int js = nt >> 1, hf = nt & 1;
            pha[js][0 + 2 * hf] = h01;
            pha[js][1 + 2 * hf] = h23;
            pla[js][0 + 2 * hf] = l01;
            pla[js][1 + 2 * hf] = l23;
        }

#pragma unroll
        for (int js = 0; js < 4; js++) {
#pragma unroll
            for (int ntp = 0; ntp < 4; ntp++) {
                uint32_t off = (ntp * 16 + l15) * 144 + js * 32 + lhi;
                uint32_t vhp[4], vlp[4];
                ldsm4(vhp, stg + ATV_OFF + off);
                ldsm4(vlp, stg + ATVL_OFF + off);
#pragma unroll
                for (int sub = 0; sub < 2; sub++) {
                    int nt = ntp * 2 + sub;
                    uint32_t vh2[2] = { vhp[sub], vhp[2 + sub] };
                    uint32_t vl2[2] = { vlp[sub], vlp[2 + sub] };
                    mma16816(O[nt], pha[js], vh2);
                    mma16816(O[nt], pha[js], vl2);
                    mma16816(O[nt], pla[js], vh2);
                }
            }
        }
        __syncthreads();
    }

    l0 += __shfl_xor_sync(0xFFFFFFFFu, l0, 1);
    l0 += __shfl_xor_sync(0xFFFFFFFFu, l0, 2);
    l1 += __shfl_xor_sync(0xFFFFFFFFu, l1, 1);
    l1 += __shfl_xor_sync(0xFFFFFFFFu, l1, 2);

    float inv0 = spikes[b * Tn + r0g] / l0;
    float inv1 = spikes[b * Tn + r1g] / l1;

#pragma unroll
    for (int nt = 0; nt < 8; nt++) {
        int col = h * 64 + nt * 8 + 2 * (lane & 3);
        float2 o0 = make_float2(O[nt][0] * inv0, O[nt][1] * inv0);
        float2 o1 = make_float2(O[nt][2] * inv1, O[nt][3] * inv1);
        *(float2*)&y[((size_t)(b * Tn + r0g)) * Cn + col] = o0;
        *(float2*)&y[((size_t)(b * Tn + r1g)) * Cn + col] = o1;
    }
}

// ---------------- launcher ----------------
extern "C" void kernel_launch(void* const* d_in, const int* in_sizes, int n_in,
                              void* d_out, int out_size) {
    const float* x    = (const float*)d_in[0];
    const float* Wqkv = (const float*)d_in[1];
    const float* bqkv = (const float*)d_in[2];
    const float* Wout = (const float*)d_in[3];
    const float* bout = (const float*)d_in[4];
    const float* wsur = (const float*)d_in[5];
    const float* bsur = (const float*)d_in[6];
    const float* thr  = (const float*)d_in[7];
    float* out = (float*)d_out;

    float *qkv, *spk, *y;
    __nv_bfloat16 *xh, *xl, *yh, *yl, *wqh, *wql, *woh, *wol;
    __nv_bfloat16 *qth, *qtl, *kth, *ktl, *vth, *vtl;
    cudaGetSymbolAddress((void**)&qkv, g_qkv);
    cudaGetSymbolAddress((void**)&spk, g_spk);
    cudaGetSymbolAddress((void**)&y, g_y);
    cudaGetSymbolAddress((void**)&xh, g_xh);
    cudaGetSymbolAddress((void**)&xl, g_xl);
    cudaGetSymbolAddress((void**)&yh, g_yh);
    cudaGetSymbolAddress((void**)&yl, g_yl);
    cudaGetSymbolAddress((void**)&wqh, g_wqh);
    cudaGetSymbolAddress((void**)&wql, g_wql);
    cudaGetSymbolAddress((void**)&woh, g_woh);
    cudaGetSymbolAddress((void**)&wol, g_wol);
    cudaGetSymbolAddress((void**)&qth, g_qth);
    cudaGetSymbolAddress((void**)&qtl, g_qtl);
    cudaGetSymbolAddress((void**)&kth, g_kth);
    cudaGetSymbolAddress((void**)&ktl, g_ktl);
    cudaGetSymbolAddress((void**)&vth, g_vth);
    cudaGetSymbolAddress((void**)&vtl, g_vtl);

    cudaFuncSetAttribute(mma_gemm_kernel, cudaFuncAttributeMaxDynamicSharedMemorySize, GEMM_SMEM);
    cudaFuncSetAttribute(attn_mma_kernel, cudaFuncAttributeMaxDynamicSharedMemorySize, ATTN_SMEM);

    // 1. spikes
    spike_kernel<<<MR, 256>>>(x, wsur, bsur, thr, spk);
    // 2. split-bf16 conversions
    conv_rows_kernel<<<(MR * Cn) / 256, 256>>>(x, xh, xl);
    convT_kernel<<<dim3(3 * Cn / 32, Cn / 32), dim3(32, 8)>>>(Wqkv, wqh, wql, Cn, 3 * Cn);
    // 3. qkv = x @ W_qkv + b   (tiles 128x256)
    mma_gemm_kernel<<<dim3(3 * Cn / 256, MR / 128), 512, GEMM_SMEM>>>(
        xh, xl, wqh, wql, bqkv, qkv, 3 * Cn, Cn);
    // 4. hyperbolic transform -> split-bf16 q,k,v^T
    transform_kernel<<<dim3(MR / 32, Hn), 256>>>(qkv, qth, qtl, kth, ktl, vth, vtl);
    // 5. flash attention (tensor cores)
    attn_mma_kernel<<<512, 256, ATTN_SMEM>>>(qth, qtl, kth, ktl, vth, vtl, spk, y);
    // 6. out projection
    conv_rows_kernel<<<(MR * Cn) / 256, 256>>>(y, yh, yl);
    convT_kernel<<<dim3(Cn / 32, Cn / 32), dim3(32, 8)>>>(Wout, woh, wol, Cn, Cn);
    mma_gemm_kernel<<<dim3(Cn / 256, MR / 128), 512, GEMM_SMEM>>>(
        yh, yl, woh, wol, bout, out, Cn, Cn);
}

// round 14
// speedup vs baseline: 1.0743x; 1.0743x over previous
#include <cuda_runtime.h>
#include <cuda_bf16.h>
#include <math.h>
#include <stdint.h>

// Problem constants
#define Bn 4
#define Tn 1024
#define Cn 1024
#define Hn 16
#define Dn 64
#define MR (Bn*Tn)
#define BH (Bn*Hn)

// ---------------- scratch (no allocations allowed) ----------------
__device__ float g_qkv[MR * 3 * Cn];
__device__ float g_spk[MR];
__device__ __nv_bfloat16 g_xh[MR * Cn], g_xl[MR * Cn];
__device__ __nv_bfloat16 g_yh[MR * Cn], g_yl[MR * Cn];
__device__ __nv_bfloat16 g_wqh[3 * Cn * Cn], g_wql[3 * Cn * Cn];
__device__ __nv_bfloat16 g_woh[Cn * Cn], g_wol[Cn * Cn];
__device__ __nv_bfloat16 g_qth[BH * Tn * Dn], g_qtl[BH * Tn * Dn];
__device__ __nv_bfloat16 g_kth[BH * Tn * Dn], g_ktl[BH * Tn * Dn];
__device__ __nv_bfloat16 g_vth[BH * Dn * Tn], g_vtl[BH * Dn * Tn];

// ---------------- helpers ----------------
__device__ __forceinline__ uint32_t smem_u32(const void* p) {
    uint32_t a;
    asm("{ .reg .u64 t; cvta.to.shared.u64 t, %1; cvt.u32.u64 %0, t; }" : "=r"(a) : "l"(p));
    return a;
}
__device__ __forceinline__ void cp16(uint32_t dst, const void* src) {
    asm volatile("cp.async.cg.shared.global [%0], [%1], 16;" :: "r"(dst), "l"(src));
}
__device__ __forceinline__ void cp_commit() {
    asm volatile("cp.async.commit_group;" ::: "memory");
}
template <int N>
__device__ __forceinline__ void cp_wait() {
    asm volatile("cp.async.wait_group %0;" :: "n"(N) : "memory");
}
__device__ __forceinline__ void mma16816(float* d, const uint32_t* a, const uint32_t* b) {
    asm volatile(
        "mma.sync.aligned.m16n8k16.row.col.f32.bf16.bf16.f32 "
        "{%0,%1,%2,%3}, {%4,%5,%6,%7}, {%8,%9}, {%0,%1,%2,%3};"
        : "+f"(d[0]), "+f"(d[1]), "+f"(d[2]), "+f"(d[3])
        : "r"(a[0]), "r"(a[1]), "r"(a[2]), "r"(a[3]), "r"(b[0]), "r"(b[1]));
}
__device__ __forceinline__ void ldsm4(uint32_t* r, uint32_t addr) {
    asm volatile("ldmatrix.sync.aligned.m8n8.x4.shared.b16 {%0,%1,%2,%3}, [%4];"
        : "=r"(r[0]), "=r"(r[1]), "=r"(r[2]), "=r"(r[3]) : "r"(addr));
}
__device__ __forceinline__ uint32_t pack_bf16x2(float hi, float lo) {
    uint32_t r;
    asm("cvt.rn.bf16x2.f32 %0, %1, %2;" : "=r"(r) : "f"(hi), "f"(lo));
    return r;
}

// ---------------- fast math (FMA-pipe log/exp) ----------------
__device__ __forceinline__ float fast_log(float a) {   // a >= 1
    int i = __float_as_int(a);
    int e = (i >> 23) - 126;
    float m = __int_as_float((i & 0x007FFFFF) | 0x3F000000);
    if (m < 0.70710678118f) { m = m + m; e -= 1; }
    float x = m - 1.0f;
    float z = x * x;
    float y = 7.0376836292e-2f;
    y = fmaf(y, x, -1.1514610310e-1f);
    y = fmaf(y, x,  1.1676998740e-1f);
    y = fmaf(y, x, -1.2420140846e-1f);
    y = fmaf(y, x,  1.4249322787e-1f);
    y = fmaf(y, x, -1.6668057665e-1f);
    y = fmaf(y, x,  2.0000714765e-1f);
    y = fmaf(y, x, -2.4999993993e-1f);
    y = fmaf(y, x,  3.3333331174e-1f);
    y = y * x * z;
    float ef = (float)e;
    y = fmaf(ef, -2.12194440e-4f, y);
    y = fmaf(-0.5f, z, y);
    float r = x + y;
    return fmaf(ef, 0.693359375f, r);
}
__device__ __forceinline__ float fast_exp_neg(float zin) {  // zin <= 0
    float z = fmaxf(zin, -80.f);
    float fn = fmaf(z, 1.44269504089f, 12582912.f);
    int n = __float_as_int(fn) - 0x4B400000;
    float nf = fn - 12582912.f;
    float r = fmaf(nf, -0.693359375f, z);
    r = fmaf(nf, 2.12194440e-4f, r);
    float y = 1.9875691500e-4f;
    y = fmaf(y, r, 1.3981999507e-3f);
    y = fmaf(y, r, 8.3334519073e-3f);
    y = fmaf(y, r, 4.1665795894e-2f);
    y = fmaf(y, r, 1.6666665459e-1f);
    y = fmaf(y, r, 5.0000001201e-1f);
    float res = fmaf(y * r, r, r) + 1.0f;
    return res * __int_as_float((n + 127) << 23);
}
__device__ __forceinline__ float score_p(float x) {
    float xx = fmaxf(x, 1.0000001f);
    float s2 = fmaf(xx, xx, -1.f);
    float sq;
    asm("sqrt.approx.f32 %0, %1;" : "=f"(sq) : "f"(s2));
    float dist = fast_log(xx + sq);
    return fast_exp_neg(dist * dist * -0.125f);
}

// ---------------- spike / surrogate ----------------
__global__ void spike_kernel(const float* __restrict__ x, const float* __restrict__ w_sur,
                             const float* __restrict__ b_sur, const float* __restrict__ threshold,
                             float* __restrict__ spikes) {
    __shared__ float red[256];
    int bt = blockIdx.x;
    const float* xr = &x[(size_t)bt * Cn];
    float s = 0.f;
    for (int c = threadIdx.x; c < Cn; c += 256) s += xr[c] * w_sur[c];
    red[threadIdx.x] = s;
    __syncthreads();
    for (int o = 128; o; o >>= 1) {
        if (threadIdx.x < o) red[threadIdx.x] += red[threadIdx.x + o];
        __syncthreads();
    }
    if (threadIdx.x == 0) {
        float imp = 1.f / (1.f + expf(-(red[0] + b_sur[0])));
        spikes[bt] = imp > threshold[0] ? 1.f : 0.f;
    }
}

// ---------------- fp32 -> bf16 hi/lo converters ----------------
__global__ void conv_rows_kernel(const float* __restrict__ A,
                                 __nv_bfloat16* __restrict__ h, __nv_bfloat16* __restrict__ l) {
    int i = blockIdx.x * 256 + threadIdx.x;
    float v = A[i];
    __nv_bfloat16 hh = __float2bfloat16(v);
    h[i] = hh;
    l[i] = __float2bfloat16(v - __bfloat162float(hh));
}
__global__ void convT_kernel(const float* __restrict__ W,
                             __nv_bfloat16* __restrict__ th, __nv_bfloat16* __restrict__ tl,
                             int K, int N) {
    __shared__ float t[32][33];
    int n0 = blockIdx.x * 32, k0 = blockIdx.y * 32;
    for (int i = threadIdx.y; i < 32; i += 8)
        t[i][threadIdx.x] = W[(size_t)(k0 + i) * N + n0 + threadIdx.x];
    __syncthreads();
    for (int i = threadIdx.y; i < 32; i += 8) {
        float v = t[threadIdx.x][i];
        __nv_bfloat16 hh = __float2bfloat16(v);
        size_t o = (size_t)(n0 + i) * K + k0 + threadIdx.x;
        th[o] = hh;
        tl[o] = __float2bfloat16(v - __bfloat162float(hh));
    }
}

// ---------------- mma.sync split-bf16 GEMM (R6 best-measured: 2-stage, 256 thr, scalar LDS) ----------------
#define AH_OFF 0
#define AL_OFF 10240
#define BH_OFF 20480
#define BL_OFF 30720
#define STAGE_B 40960
#define GEMM_SMEM (2 * STAGE_B)

__global__ __launch_bounds__(256) void mma_gemm_kernel(
    const __nv_bfloat16* __restrict__ Ah, const __nv_bfloat16* __restrict__ Al,
    const __nv_bfloat16* __restrict__ Bh, const __nv_bfloat16* __restrict__ Bl,
    const float* __restrict__ bias, float* __restrict__ Cm, int N, int K) {
    extern __shared__ __align__(128) char smem[];
    uint32_t sb = smem_u32(smem);

    int tid = threadIdx.x;
    int lane = tid & 31;
    int w = tid >> 5;
    int wm = w & 3;
    int wn = w >> 2;
    int bm = blockIdx.y * 128;
    int bn = blockIdx.x * 128;

    float acc[2][8][4];
#pragma unroll
    for (int mt = 0; mt < 2; mt++)
#pragma unroll
        for (int nt = 0; nt < 8; nt++)
#pragma unroll
            for (int q = 0; q < 4; q++) acc[mt][nt][q] = 0.f;

    int NK = K / 32;

    auto load_stage = [&](int kc, int s) {
        uint32_t base = sb + s * STAGE_B;
        int k0 = kc * 32;
#pragma unroll
        for (int it = 0; it < 2; it++) {
            int lin = it * 256 + tid;
            int r = lin >> 2, c = lin & 3;
            uint32_t so = (uint32_t)(r * 80 + c * 16);
            size_t go = (size_t)(bm + r) * K + k0 + c * 8;
            cp16(base + AH_OFF + so, Ah + go);
            cp16(base + AL_OFF + so, Al + go);
        }
#pragma unroll
        for (int it = 0; it < 2; it++) {
            int lin = it * 256 + tid;
            int r = lin >> 2, c = lin & 3;
            uint32_t so = (uint32_t)(r * 80 + c * 16);
            size_t go = (size_t)(bn + r) * K + k0 + c * 8;
            cp16(base + BH_OFF + so, Bh + go);
            cp16(base + BL_OFF + so, Bl + go);
        }
        cp_commit();
    };

    load_stage(0, 0);

    int arow = wm * 32 + (lane >> 2);
    int kcol = 2 * (lane & 3);
    int brow = wn * 64 + (lane >> 2);

    for (int kc = 0; kc < NK; kc++) {
        if (kc + 1 < NK) { load_stage(kc + 1, (kc + 1) & 1); cp_wait<1>(); }
        else cp_wait<0>();
        __syncthreads();

        const char* sm = (const char*)smem + (kc & 1) * STAGE_B;

#pragma unroll
        for (int ks = 0; ks < 2; ks++) {
            int kb = (ks * 16 + kcol) * 2;
            uint32_t ah[2][4], al[2][4];
#pragma unroll
            for (int mt = 0; mt < 2; mt++) {
                int r0 = (arow + mt * 16) * 80 + kb;
                ah[mt][0] = *(const uint32_t*)(sm + AH_OFF + r0);
                ah[mt][1] = *(const uint32_t*)(sm + AH_OFF + r0 + 8 * 80);
                ah[mt][2] = *(const uint32_t*)(sm + AH_OFF + r0 + 16);
                ah[mt][3] = *(const uint32_t*)(sm + AH_OFF + r0 + 8 * 80 + 16);
                al[mt][0] = *(const uint32_t*)(sm + AL_OFF + r0);
                al[mt][1] = *(const uint32_t*)(sm + AL_OFF + r0 + 8 * 80);
                al[mt][2] = *(const uint32_t*)(sm + AL_OFF + r0 + 16);
                al[mt][3] = *(const uint32_t*)(sm + AL_OFF + r0 + 8 * 80 + 16);
            }
#pragma unroll
            for (int nt = 0; nt < 8; nt++) {
                int r0 = (brow + nt * 8) * 80 + kb;
                uint32_t bh[2], bl[2];
                bh[0] = *(const uint32_t*)(sm + BH_OFF + r0);
                bh[1] = *(const uint32_t*)(sm + BH_OFF + r0 + 16);
                bl[0] = *(const uint32_t*)(sm + BL_OFF + r0);
                bl[1] = *(const uint32_t*)(sm + BL_OFF + r0 + 16);
#pragma unroll
                for (int mt = 0; mt < 2; mt++) {
                    mma16816(acc[mt][nt], ah[mt], bh);
                    mma16816(acc[mt][nt], ah[mt], bl);
                    mma16816(acc[mt][nt], al[mt], bh);
                }
            }
        }
        __syncthreads();
    }

#pragma unroll
    for (int mt = 0; mt < 2; mt++) {
        int m0 = bm + wm * 32 + mt * 16 + (lane >> 2);
#pragma unroll
        for (int nt = 0; nt < 8; nt++) {
            int c0 = bn + wn * 64 + nt * 8 + 2 * (lane & 3);
            float b0 = bias[c0], b1 = bias[c0 + 1];
            float* p0 = Cm + (size_t)m0 * N + c0;
            p0[0] = acc[mt][nt][0] + b0;
            p0[1] = acc[mt][nt][1] + b1;
            float* p1 = p0 + 8 * (size_t)N;
            p1[0] = acc[mt][nt][2] + b0;
            p1[1] = acc[mt][nt][3] + b1;
        }
    }
}

// ---------------- expmap0 transform: 32 tokens x 1 head per block ----------------
__global__ __launch_bounds__(256) void transform_kernel(
    const float* __restrict__ qkv,
    __nv_bfloat16* __restrict__ qth, __nv_bfloat16* __restrict__ qtl,
    __nv_bfloat16* __restrict__ kth, __nv_bfloat16* __restrict__ ktl,
    __nv_bfloat16* __restrict__ vth, __nv_bfloat16* __restrict__ vtl) {
    __shared__ float vs[32][67];

    int tb = blockIdx.x;
    int h = blockIdx.y;
    int w = threadIdx.x >> 5;
    int lane = threadIdx.x & 31;

    int bt0 = tb * 32;
    int b = bt0 / Tn;
    int t0 = bt0 % Tn;
    int bh = b * Hn + h;

#pragma unroll
    for (int it = 0; it < 4; it++) {
        int tl = it * 8 + w;
        int bt = bt0 + tl;
        int t = t0 + tl;

        const float* base = &qkv[(size_t)bt * (3 * Cn) + h * Dn];
        float2 uq = ((const float2*)base)[lane];
        float2 uk = ((const float2*)(base + Cn))[lane];
        float2 uv = ((const float2*)(base + 2 * Cn))[lane];

        float sq = uq.y * uq.y + (lane ? uq.x * uq.x : 0.f);
        float sk = uk.y * uk.y + (lane ? uk.x * uk.x : 0.f);
#pragma unroll
        for (int off = 16; off; off >>= 1) {
            sq += __shfl_xor_sync(0xFFFFFFFFu, sq, off);
            sk += __shfl_xor_sync(0xFFFFFFFFu, sk, off);
        }
        float u0q = __shfl_sync(0xFFFFFFFFu, uq.x, 0);
        float u0k = __shfl_sync(0xFFFFFFFFu, uk.x, 0);

        float nq = sqrtf(fmaxf(sq - u0q * u0q, 1e-8f));
        float nk = sqrtf(fmaxf(sk - u0k * u0k, 1e-8f));
        float fq = sinhf(nq) / nq;
        float fk = sinhf(nk) / nk;
        float tmq = coshf(nq);
        float tmk = coshf(nk);

        float2 oq, ok;
        oq.x = lane ? fq * uq.x : tmq;
        oq.y = fq * uq.y;
        ok.x = lane ? -fk * uk.x : tmk;
        ok.y = -fk * uk.y;

        size_t out = ((size_t)bh * Tn + t) * Dn;
        __nv_bfloat16 qx = __float2bfloat16(oq.x), qy = __float2bfloat16(oq.y);
        ((__nv_bfloat162*)(qth + out))[lane] = __nv_bfloat162(qx, qy);
        ((__nv_bfloat162*)(qtl + out))[lane] = __nv_bfloat162(
            __float2bfloat16(oq.x - __bfloat162float(qx)), __float2bfloat16(oq.y - __bfloat162float(qy)));
        __nv_bfloat16 kx = __float2bfloat16(ok.x), ky = __float2bfloat16(ok.y);
        ((__nv_bfloat162*)(kth + out))[lane] = __nv_bfloat162(kx, ky);
        ((__nv_bfloat162*)(ktl + out))[lane] = __nv_bfloat162(
            __float2bfloat16(ok.x - __bfloat162float(kx)), __float2bfloat16(ok.y - __bfloat162float(ky)));

        vs[tl][2 * lane] = uv.x;
        vs[tl][2 * lane + 1] = uv.y;
    }
    __syncthreads();

#pragma unroll
    for (int rep = 0; rep < 8; rep++) {
        int idx = rep * 256 + threadIdx.x;
        int d = idx >> 5, t = idx & 31;
        float v = vs[t][d];
        __nv_bfloat16 hh = __float2bfloat16(v);
        size_t o = ((size_t)bh * Dn + d) * Tn + t0 + t;
        vth[o] = hh;
        vtl[o] = __float2bfloat16(v - __bfloat162float(hh));
    }
}

// ---------------- flash attention on mma.sync (R10) + fused y-split epilogue ----------------
#define ATK_OFF 0
#define ATKL_OFF 9216
#define ATV_OFF 18432
#define ATVL_OFF 27648
#define ATSTG 36864
#define ATTN_SMEM (2 * ATSTG)

__global__ __launch_bounds__(256) void attn_mma_kernel(
    const __nv_bfloat16* __restrict__ qth, const __nv_bfloat16* __restrict__ qtl,
    const __nv_bfloat16* __restrict__ kth, const __nv_bfloat16* __restrict__ ktl,
    const __nv_bfloat16* __restrict__ vth, const __nv_bfloat16* __restrict__ vtl,
    const float* __restrict__ spikes,
    __nv_bfloat16* __restrict__ yh, __nv_bfloat16* __restrict__ yl) {
    extern __shared__ __align__(128) char smem[];
    uint32_t sb = smem_u32(smem);

    int tid = threadIdx.x;
    int lane = tid & 31;
    int w = tid >> 5;

    int idx = blockIdx.x;
    int qt = 7 - (idx >> 6);
    int bh = idx & 63;
    int b = bh >> 4, h = bh & 15;
    int q0 = qt * 128;

    size_t qoff = ((size_t)bh * Tn + q0) * Dn;
#pragma unroll
    for (int it = 0; it < 4; it++) {
        int lin = it * 256 + tid;
        int r = lin >> 3, c = lin & 7;
        cp16(sb + (uint32_t)(r * 144 + c * 16), qth + qoff + r * 64 + c * 8);
        cp16(sb + 18432u + (uint32_t)(r * 144 + c * 16), qtl + qoff + r * 64 + c * 8);
    }
    cp_commit();

    size_t kbase = (size_t)bh * Tn * Dn;
    size_t vbase = (size_t)bh * Dn * Tn;
    auto load_tile = [&](int t, int s) {
        uint32_t base = sb + s * ATSTG;
        int k0 = t * 64;
#pragma unroll
        for (int it = 0; it < 2; it++) {
            int lin = it * 256 + tid;
            int r = lin >> 3, c = lin & 7;
            uint32_t so = (uint32_t)(r * 144 + c * 16);
            cp16(base + ATK_OFF + so, kth + kbase + (size_t)(k0 + r) * 64 + c * 8);
            cp16(base + ATKL_OFF + so, ktl + kbase + (size_t)(k0 + r) * 64 + c * 8);
            cp16(base + ATV_OFF + so, vth + vbase + (size_t)r * Tn + k0 + c * 8);
            cp16(base + ATVL_OFF + so, vtl + vbase + (size_t)r * Tn + k0 + c * 8);
        }
        cp_commit();
    };

    load_tile(0, 1);

    cp_wait<1>();
    __syncthreads();

    int rowi = lane >> 2;
    int qrow = w * 16 + rowi;
    uint32_t qfh[4][4], qfl[4][4];
#pragma unroll
    for (int ks = 0; ks < 4; ks++) {
        int cb = (ks * 16 + 2 * (lane & 3)) * 2;
        const char* qs = smem;
        const char* qsl = smem + 18432;
        qfh[ks][0] = *(const uint32_t*)(qs + qrow * 144 + cb);
        qfh[ks][1] = *(const uint32_t*)(qs + (qrow + 8) * 144 + cb);
        qfh[ks][2] = *(const uint32_t*)(qs + qrow * 144 + cb + 16);
        qfh[ks][3] = *(const uint32_t*)(qs + (qrow + 8) * 144 + cb + 16);
        qfl[ks][0] = *(const uint32_t*)(qsl + qrow * 144 + cb);
        qfl[ks][1] = *(const uint32_t*)(qsl + (qrow + 8) * 144 + cb);
        qfl[ks][2] = *(const uint32_t*)(qsl + qrow * 144 + cb + 16);
        qfl[ks][3] = *(const uint32_t*)(qsl + (qrow + 8) * 144 + cb + 16);
    }
    __syncthreads();

    float O[8][4];
#pragma unroll
    for (int nt = 0; nt < 8; nt++)
#pragma unroll
        for (int q = 0; q < 4; q++) O[nt][q] = 0.f;
    float l0 = 0.f, l1 = 0.f;

    int r0g = q0 + w * 16 + rowi;
    int r1g = r0g + 8;

    uint32_t l15 = lane & 15;
    uint32_t lhi = (lane >> 4) * 16;

    int ntiles = qt * 2 + 2;
    for (int t = 0; t < ntiles; t++) {
        if (t + 1 < ntiles) { load_tile(t + 1, t & 1); cp_wait<1>(); }
        else cp_wait<0>();
        __syncthreads();

        int s = (t + 1) & 1;
        uint32_t stg = sb + s * ATSTG;
        int k0 = t * 64;

        float S[8][4];
#pragma unroll
        for (int nt = 0; nt < 8; nt++)
#pragma unroll
            for (int q = 0; q < 4; q++) S[nt][q] = 0.f;
#pragma unroll
        for (int ks = 0; ks < 4; ks++) {
#pragma unroll
            for (int ntp = 0; ntp < 4; ntp++) {
                uint32_t off = (ntp * 16 + l15) * 144 + ks * 32 + lhi;
                uint32_t bhp[4], blp[4];
                ldsm4(bhp, stg + ATK_OFF + off);
                ldsm4(blp, stg + ATKL_OFF + off);
#pragma unroll
                for (int sub = 0; sub < 2; sub++) {
                    int nt = ntp * 2 + sub;
                    uint32_t bh2[2] = { bhp[sub], bhp[2 + sub] };
                    uint32_t bl2[2] = { blp[sub], blp[2 + sub] };
                    mma16816(S[nt], qfh[ks], bh2);
                    mma16816(S[nt], qfh[ks], bl2);
                    mma16816(S[nt], qfl[ks], bh2);
                }
            }
        }

        uint32_t pha[4][4], pla[4][4];
#pragma unroll
        for (int nt = 0; nt < 8; nt++) {
            int jj0 = k0 + nt * 8 + 2 * (lane & 3);
            float p0 = score_p(S[nt][0]);
            float p1 = score_p(S[nt][1]);
            float p2 = score_p(S[nt][2]);
            float p3 = score_p(S[nt][3]);
            p0 = (jj0 <= r0g) ? p0 : 0.f;
            p1 = (jj0 + 1 <= r0g) ? p1 : 0.f;
            p2 = (jj0 <= r1g) ? p2 : 0.f;
            p3 = (jj0 + 1 <= r1g) ? p3 : 0.f;
            l0 += p0 + p1;
            l1 += p2 + p3;
            uint32_t h01 = pack_bf16x2(p1, p0);
            uint32_t h23 = pack_bf16x2(p3, p2);
            float f0 = __int_as_float(h01 << 16);
            float f1 = __int_as_float(h01 & 0xFFFF0000u);
            float f2 = __int_as_float(h23 << 16);
            float f3 = __int_as_float(h23 & 0xFFFF0000u);
            uint32_t l01 = pack_bf16x2(p1 - f1, p0 - f0);
            uint32_t l23 = pack_bf16x2(p3 - f3, p2 - f2);
            int js = nt >> 1, hf = nt & 1;
            pha[js][0 + 2 * hf] = h01;
            pha[js][1 + 2 * hf] = h23;
            pla[js][0 + 2 * hf] = l01;
            pla[js][1 + 2 * hf] = l23;
        }

#pragma unroll
        for (int js = 0; js < 4; js++) {
#pragma unroll
            for (int ntp = 0; ntp < 4; ntp++) {
                uint32_t off = (ntp * 16 + l15) * 144 + js * 32 + lhi;
                uint32_t vhp[4], vlp[4];
                ldsm4(vhp, stg + ATV_OFF + off);
                ldsm4(vlp, stg + ATVL_OFF + off);
#pragma unroll
                for (int sub = 0; sub < 2; sub++) {
                    int nt = ntp * 2 + sub;
                    uint32_t vh2[2] = { vhp[sub], vhp[2 + sub] };
                    uint32_t vl2[2] = { vlp[sub], vlp[2 + sub] };
                    mma16816(O[nt], pha[js], vh2);
                    mma16816(O[nt], pha[js], vl2);
                    mma16816(O[nt], pla[js], vh2);
                }
            }
        }
        __syncthreads();
    }

    l0 += __shfl_xor_sync(0xFFFFFFFFu, l0, 1);
    l0 += __shfl_xor_sync(0xFFFFFFFFu, l0, 2);
    l1 += __shfl_xor_sync(0xFFFFFFFFu, l1, 1);
    l1 += __shfl_xor_sync(0xFFFFFFFFu, l1, 2);

    float inv0 = spikes[b * Tn + r0g] / l0;
    float inv1 = spikes[b * Tn + r1g] / l1;

    // ---- fused epilogue: write y directly as bf16 hi/lo ----
#pragma unroll
    for (int nt = 0; nt < 8; nt++) {
        int col = h * 64 + nt * 8 + 2 * (lane & 3);
        size_t o0 = ((size_t)(b * Tn + r0g)) * Cn + col;
        size_t o1 = ((size_t)(b * Tn + r1g)) * Cn + col;
        float v00 = O[nt][0] * inv0, v01 = O[nt][1] * inv0;
        float v10 = O[nt][2] * inv1, v11 = O[nt][3] * inv1;
        uint32_t h0 = pack_bf16x2(v01, v00);           // {hi: v01, lo: v00}
        uint32_t h1 = pack_bf16x2(v11, v10);
        float r00 = v00 - __int_as_float(h0 << 16);
        float r01 = v01 - __int_as_float(h0 & 0xFFFF0000u);
        float r10 = v10 - __int_as_float(h1 << 16);
        float r11 = v11 - __int_as_float(h1 & 0xFFFF0000u);
        *(uint32_t*)(yh + o0) = h0;
        *(uint32_t*)(yh + o1) = h1;
        *(uint32_t*)(yl + o0) = pack_bf16x2(r01, r00);
        *(uint32_t*)(yl + o1) = pack_bf16x2(r11, r10);
    }
}

// ---------------- launcher ----------------
extern "C" void kernel_launch(void* const* d_in, const int* in_sizes, int n_in,
                              void* d_out, int out_size) {
    const float* x    = (const float*)d_in[0];
    const float* Wqkv = (const float*)d_in[1];
    const float* bqkv = (const float*)d_in[2];
    const float* Wout = (const float*)d_in[3];
    const float* bout = (const float*)d_in[4];
    const float* wsur = (const float*)d_in[5];
    const float* bsur = (const float*)d_in[6];
    const float* thr  = (const float*)d_in[7];
    float* out = (float*)d_out;

    float *qkv, *spk;
    __nv_bfloat16 *xh, *xl, *yh, *yl, *wqh, *wql, *woh, *wol;
    __nv_bfloat16 *qth, *qtl, *kth, *ktl, *vth, *vtl;
    cudaGetSymbolAddress((void**)&qkv, g_qkv);
    cudaGetSymbolAddress((void**)&spk, g_spk);
    cudaGetSymbolAddress((void**)&xh, g_xh);
    cudaGetSymbolAddress((void**)&xl, g_xl);
    cudaGetSymbolAddress((void**)&yh, g_yh);
    cudaGetSymbolAddress((void**)&yl, g_yl);
    cudaGetSymbolAddress((void**)&wqh, g_wqh);
    cudaGetSymbolAddress((void**)&wql, g_wql);
    cudaGetSymbolAddress((void**)&woh, g_woh);
    cudaGetSymbolAddress((void**)&wol, g_wol);
    cudaGetSymbolAddress((void**)&qth, g_qth);
    cudaGetSymbolAddress((void**)&qtl, g_qtl);
    cudaGetSymbolAddress((void**)&kth, g_kth);
    cudaGetSymbolAddress((void**)&ktl, g_ktl);
    cudaGetSymbolAddress((void**)&vth, g_vth);
    cudaGetSymbolAddress((void**)&vtl, g_vtl);

    cudaFuncSetAttribute(mma_gemm_kernel, cudaFuncAttributeMaxDynamicSharedMemorySize, GEMM_SMEM);
    cudaFuncSetAttribute(attn_mma_kernel, cudaFuncAttributeMaxDynamicSharedMemorySize, ATTN_SMEM);

    // 1. spikes
    spike_kernel<<<MR, 256>>>(x, wsur, bsur, thr, spk);
    // 2. split-bf16 conversions
    conv_rows_kernel<<<(MR * Cn) / 256, 256>>>(x, xh, xl);
    convT_kernel<<<dim3(3 * Cn / 32, Cn / 32), dim3(32, 8)>>>(Wqkv, wqh, wql, Cn, 3 * Cn);
    convT_kernel<<<dim3(Cn / 32, Cn / 32), dim3(32, 8)>>>(Wout, woh, wol, Cn, Cn);
    // 3. qkv = x @ W_qkv + b
    mma_gemm_kernel<<<dim3(3 * Cn / 128, MR / 128), 256, GEMM_SMEM>>>(
        xh, xl, wqh, wql, bqkv, qkv, 3 * Cn, Cn);
    // 4. hyperbolic transform -> split-bf16 q,k,v^T
    transform_kernel<<<dim3(MR / 32, Hn), 256>>>(qkv, qth, qtl, kth, ktl, vth, vtl);
    // 5. flash attention (tensor cores), y emitted directly as bf16 hi/lo
    attn_mma_kernel<<<512, 256, ATTN_SMEM>>>(qth, qtl, kth, ktl, vth, vtl, spk, yh, yl);
    // 6. out projection
    mma_gemm_kernel<<<dim3(Cn / 128, MR / 128), 256, GEMM_SMEM>>>(
        yh, yl, woh, wol, bout, out, Cn, Cn);
}